// round 1
// baseline (speedup 1.0000x reference)
#include <cuda_runtime.h>
#include <math.h>

#define BB 8
#define CC 256
#define HH 128
#define WW 128
#define NHD 4
#define CGR 64
#define LP 1024
#define DQ 256

typedef unsigned long long ull;

// ---------------- scratch (device globals; no allocation allowed) ----------------
__device__ float g_xp  [BB*CC*LP];        // pooled x [b][c][1024]
__device__ float g_qn  [BB*NHD*CC*DQ];    // normalized q [bh][c][d]
__device__ float g_kn  [BB*NHD*CC*DQ];    // normalized k [bh][c][d]
__device__ float g_sim [BB*NHD*CC*CC];    // sim -> W (in place) [bh][c][e]
__device__ float g_bias[NHD*CC*CC];       // cpb bias [h][i][j]
__device__ float g_wvt [BB*NHD*CC*CC];    // (W folded with v_pw)^T [bh][j][c]
__device__ float g_mt  [BB*NHD*CC*CC];    // Mt [bh][j][o]
__device__ float g_wb  [BB*NHD*CC];       // W @ v_pw_b [bh][c]
__device__ float g_cvec[BB*NHD*CC];       // per-(bh,o) constant incl proj_b
__device__ float g_scwT[CC*CC];           // sc_w transposed [c][o]

// ---------------- small helpers ----------------
__device__ __forceinline__ ull pack2(float lo, float hi) {
    ull r; asm("mov.b64 %0, {%1, %2};" : "=l"(r) : "f"(lo), "f"(hi)); return r;
}
__device__ __forceinline__ void unpack2(ull v, float& lo, float& hi) {
    asm("mov.b64 {%0, %1}, %2;" : "=f"(lo), "=f"(hi) : "l"(v));
}
// Blackwell packed dual-FMA (FFMA2): 2 fp32 FMAs per instruction
__device__ __forceinline__ ull ffma2(ull a, ull b, ull c) {
    ull d; asm("fma.rn.f32x2 %0, %1, %2, %3;" : "=l"(d) : "l"(a), "l"(b), "l"(c)); return d;
}
union F4U2 { float4 f; ull u[2]; };

__device__ __forceinline__ float gelu_exact(float z) {
    return 0.5f * z * (1.0f + erff(z * 0.70710678118654752440f));
}

__device__ __forceinline__ float blk256(float v, float* red, int domax) {
    #pragma unroll
    for (int off = 16; off; off >>= 1) {
        float o = __shfl_xor_sync(0xffffffffu, v, off);
        v = domax ? fmaxf(v, o) : (v + o);
    }
    int lane = threadIdx.x & 31, w = threadIdx.x >> 5;
    __syncthreads();
    if (lane == 0) red[w] = v;
    __syncthreads();
    float r = red[0];
    #pragma unroll
    for (int i = 1; i < 8; i++) r = domax ? fmaxf(r, red[i]) : (r + red[i]);
    return r;
}

// ---------------- K0: 4x4 maxpool ----------------
__global__ void pool_kernel(const float* __restrict__ x) {
    int idx = blockIdx.x * blockDim.x + threadIdx.x;
    if (idx >= BB*CC*LP) return;
    int l = idx & 1023, bc = idx >> 10;
    int py = l >> 5, px = l & 31;
    const float* xp = x + (size_t)bc * HH * WW + py * 4 * WW + px * 4;
    float m = -1e30f;
    #pragma unroll
    for (int dy = 0; dy < 4; dy++)
        #pragma unroll
        for (int dx = 0; dx < 4; dx++)
            m = fmaxf(m, xp[dy * WW + dx]);
    g_xp[idx] = m;
}

// ---------------- K_bias: CPB relative-position bias ----------------
__global__ void cpb_kernel(const float* __restrict__ w1, const float* __restrict__ b1,
                           const float* __restrict__ w2) {
    int idx = blockIdx.x * blockDim.x + threadIdx.x; // over 256*256 (i,j)
    if (idx >= CC*CC) return;
    int j = idx & 255, i = idx >> 8;
    float d = (float)(j - i) * (8.0f / 255.0f);
    float rel = copysignf(log2f(fabsf(d) + 1.0f) * (1.0f / 3.0f), d);
    float acc0 = 0.f, acc1 = 0.f, acc2 = 0.f, acc3 = 0.f;
    #pragma unroll 8
    for (int t = 0; t < 64; t++) {
        float hdn = fmaxf(rel * w1[t] + b1[t], 0.0f);
        acc0 += hdn * w2[t*4+0]; acc1 += hdn * w2[t*4+1];
        acc2 += hdn * w2[t*4+2]; acc3 += hdn * w2[t*4+3];
    }
    g_bias[0*65536 + idx] = 1.0f / (1.0f + expf(-acc0));
    g_bias[1*65536 + idx] = 1.0f / (1.0f + expf(-acc1));
    g_bias[2*65536 + idx] = 1.0f / (1.0f + expf(-acc2));
    g_bias[3*65536 + idx] = 1.0f / (1.0f + expf(-acc3));
}

// ---------------- K1: grouped 1x1 conv for q,k + per-(b,h,c) l2 normalize ----------------
__global__ void qk_kernel(const float* __restrict__ qw, const float* __restrict__ qb,
                          const float* __restrict__ kw, const float* __restrict__ kb) {
    int bhc = blockIdx.x;            // (b*4+h)*256 + c
    int c = bhc & 255, bh = bhc >> 8;
    int h = bh & 3, b = bh >> 2;
    int d = threadIdx.x;
    const float* w    = blockIdx.y ? kw : qw;
    const float* bias = blockIdx.y ? kb : qb;
    float* outp       = blockIdx.y ? g_kn : g_qn;
    int g = c >> 6, ci = c & 63;
    const float* wrow = w + (g * CGR + ci) * CGR;
    const float* xpb  = g_xp + ((size_t)b * CC + g * CGR) * LP + h * DQ + d;
    float acc = bias[c];
    #pragma unroll 8
    for (int ji = 0; ji < CGR; ji++) acc += wrow[ji] * xpb[(size_t)ji * LP];
    __shared__ float red[8];
    float ss = blk256(acc * acc, red, 0);
    float inv = 1.0f / fmaxf(sqrtf(ss), 1e-12f);
    outp[(size_t)bhc * DQ + d] = acc * inv;
}

// ---------------- batched 256x256x256 NT GEMM (C[i,j] = sum_k A[i,k]*B[j,k]) ----------------
// mode 0: sim = qn @ kn^T * scale_h + bias_h   mode 1: Mt = wvt @ proj_w^T
__global__ void gemm_nt_kernel(int mode, const float* __restrict__ Bext,
                               const float* __restrict__ ls) {
    int z = blockIdx.z;
    const float *Az, *Bz; float* Cz; const float* bz = nullptr; float scale = 1.0f;
    if (mode == 0) {
        Az = g_qn + (size_t)z * 65536; Bz = g_kn + (size_t)z * 65536;
        Cz = g_sim + (size_t)z * 65536;
        bz = g_bias + (size_t)(z & 3) * 65536;
        scale = expf(fminf(ls[z & 3], 4.6051701859880913680f));   // clamp at log(100)
    } else {
        Az = g_wvt + (size_t)z * 65536; Bz = Bext;
        Cz = g_mt + (size_t)z * 65536;
    }
    int i0 = blockIdx.y * 64, j0 = blockIdx.x * 64;
    __shared__ float As[16][68], Bs[16][68];
    int t = threadIdx.x;
    int tx = t & 15, ty = t >> 4;
    float cr[4][4] = {};
    int e = t * 4, lkk = e & 15, lii = e >> 4;
    for (int k0 = 0; k0 < 256; k0 += 16) {
        float4 av = *(const float4*)(Az + (size_t)(i0 + lii) * 256 + k0 + lkk);
        float4 bv = *(const float4*)(Bz + (size_t)(j0 + lii) * 256 + k0 + lkk);
        As[lkk+0][lii] = av.x; As[lkk+1][lii] = av.y; As[lkk+2][lii] = av.z; As[lkk+3][lii] = av.w;
        Bs[lkk+0][lii] = bv.x; Bs[lkk+1][lii] = bv.y; Bs[lkk+2][lii] = bv.z; Bs[lkk+3][lii] = bv.w;
        __syncthreads();
        #pragma unroll
        for (int kk = 0; kk < 16; kk++) {
            float4 a4 = *(const float4*)&As[kk][ty * 4];
            float4 b4 = *(const float4*)&Bs[kk][tx * 4];
            float ar[4] = {a4.x, a4.y, a4.z, a4.w};
            float br[4] = {b4.x, b4.y, b4.z, b4.w};
            #pragma unroll
            for (int r = 0; r < 4; r++)
                #pragma unroll
                for (int s = 0; s < 4; s++) cr[r][s] += ar[r] * br[s];
        }
        __syncthreads();
    }
    #pragma unroll
    for (int r = 0; r < 4; r++) {
        int i = i0 + ty * 4 + r, j = j0 + tx * 4;
        float4 v;
        v.x = cr[r][0] * scale; v.y = cr[r][1] * scale;
        v.z = cr[r][2] * scale; v.w = cr[r][3] * scale;
        if (bz) {
            const float4 bb = *(const float4*)(bz + (size_t)i * 256 + j);
            v.x += bb.x; v.y += bb.y; v.z += bb.z; v.w += bb.w;
        }
        *(float4*)(Cz + (size_t)i * 256 + j) = v;
    }
}

// ---------------- K2: double softmax over last dim (in place on g_sim) ----------------
__global__ void dsoftmax_kernel() {
    float* rowp = g_sim + (size_t)blockIdx.x * 256;
    int t = threadIdx.x;
    __shared__ float red[8];
    float v = rowp[t];
    float m = blk256(v, red, 1);
    float e = expf(v - m);
    float s = blk256(e, red, 0);
    float p = e / s;                         // softmax(sim)
    float m2 = blk256(-p, red, 1);           // softmax(1-p) == softmax(-p)
    float e2 = expf(-p - m2);
    float s2 = blk256(e2, red, 0);
    rowp[t] = e2 / s2;
}

// ---------------- K_wvt: fold v_pw into W, output transposed [bh][j][c] ----------------
__global__ void wvt_kernel(const float* __restrict__ vpw) {
    __shared__ float sw[256][65];
    int g = blockIdx.x, bh = blockIdx.y;
    const float* W = g_sim + (size_t)bh * 65536;
    int t = threadIdx.x;
    for (int it = 0; it < 64; it++) {
        int lin = it * 256 + t;
        int c = lin >> 6, ei = lin & 63;
        sw[c][ei] = W[(size_t)c * 256 + g * 64 + ei];
    }
    __syncthreads();
    const float* vw = vpw + g * 4096;        // [ei][jj]
    float* outb = g_wvt + (size_t)bh * 65536 + (size_t)(g * 64) * 256 + t;
    for (int jj = 0; jj < 64; jj++) {
        float acc = 0.f;
        #pragma unroll 8
        for (int ei = 0; ei < 64; ei++) acc += sw[t][ei] * vw[ei * 64 + jj];
        outb[(size_t)jj * 256] = acc;
    }
}

// ---------------- K_wb / K_cvec: constant vector from v_pw bias + proj bias ----------------
__global__ void wb_kernel(const float* __restrict__ vpb) {
    int bh = blockIdx.x, c = threadIdx.x;
    const float* W = g_sim + ((size_t)bh * 256 + c) * 256;
    float acc = 0.f;
    for (int e2 = 0; e2 < 256; e2++) acc += W[e2] * vpb[e2];
    g_wb[bh * 256 + c] = acc;
}
__global__ void cvec_kernel(const float* __restrict__ pw, const float* __restrict__ pb) {
    int bh = blockIdx.x, o = threadIdx.x;
    const float* wb = g_wb + bh * 256;
    float acc = pb[o];
    for (int c = 0; c < 256; c++) acc += pw[o * 256 + c] * wb[c];
    g_cvec[bh * 256 + o] = acc;
}

// ---------------- K_scwT: transpose shortcut weights ----------------
__global__ void scwT_kernel(const float* __restrict__ scw) {
    int idx = blockIdx.x * blockDim.x + threadIdx.x;
    if (idx >= CC*CC) return;
    int o = idx & 255, c = idx >> 8;
    g_scwT[c * 256 + o] = scw[o * 256 + c];
}

// ---------------- K5: fused dwconv + [Mt@vd, scW@x] dual GEMM + full epilogue ----------------
__global__ void __launch_bounds__(512, 1) main_kernel(
    const float* __restrict__ x, const float* __restrict__ dww,
    const float* __restrict__ dwb, const float* __restrict__ scb,
    const float* __restrict__ gamma, const float* __restrict__ beta,
    float* __restrict__ out)
{
    extern __shared__ float sm[];
    float* s_vd = sm;            // [256][64] relu(dwconv(x)+b)
    float* s_xc = sm + 16384;    // [256][64] raw x (for shortcut)
    int b = blockIdx.z, row = blockIdx.y, cb = blockIdx.x << 6;
    int tid = threadIdx.x;

    // Phase 1: depthwise 3x3 conv (SAME, zero pad) + cache center x
    for (int idx = tid; idx < 16384; idx += 512) {
        int j = idx >> 6, p = idx & 63;
        const float* xch = x + (size_t)(b * CC + j) * HH * WW;
        int col = cb + p;
        const float* wp = dww + j * 9;
        float acc = dwb[j];
        #pragma unroll
        for (int dy = -1; dy <= 1; dy++) {
            int r2 = row + dy;
            if ((unsigned)r2 < HH) {
                const float* rp = xch + r2 * WW;
                #pragma unroll
                for (int dx = -1; dx <= 1; dx++) {
                    int c2 = col + dx;
                    if ((unsigned)c2 < WW) acc += wp[(dy + 1) * 3 + dx + 1] * rp[c2];
                }
            }
        }
        s_vd[idx] = fmaxf(acc, 0.0f);
        s_xc[idx] = xch[row * WW + col];
    }
    __syncthreads();

    // Phase 2: per thread: one output channel o, 32 spatial positions, both GEMMs
    int o = tid & 255, ph = tid >> 8;
    int bh = b * NHD + (row >> 5);
    const float* Mt = g_mt + (size_t)bh * 65536 + o;
    const float* ST = g_scwT + o;
    float c1 = g_cvec[bh * 256 + o];
    float c2 = scb[o];
    ull a1[16], a2[16];
    #pragma unroll
    for (int k = 0; k < 16; k++) { a1[k] = pack2(c1, c1); a2[k] = pack2(c2, c2); }
    const float* vb = s_vd + ph * 32;
    const float* xb = s_xc + ph * 32;
    #pragma unroll 2
    for (int j = 0; j < 256; j++) {
        float w1 = Mt[(size_t)j * 256];
        float w2 = ST[(size_t)j * 256];
        ull w1p = pack2(w1, w1), w2p = pack2(w2, w2);
        const float4* v4 = (const float4*)(vb + j * 64);
        const float4* x4 = (const float4*)(xb + j * 64);
        #pragma unroll
        for (int k = 0; k < 8; k++) {
            F4U2 a; a.f = v4[k];
            a1[2*k]   = ffma2(w1p, a.u[0], a1[2*k]);
            a1[2*k+1] = ffma2(w1p, a.u[1], a1[2*k+1]);
            F4U2 xx; xx.f = x4[k];
            a2[2*k]   = ffma2(w2p, xx.u[0], a2[2*k]);
            a2[2*k+1] = ffma2(w2p, xx.u[1], a2[2*k+1]);
        }
    }

    // Epilogue: GELU + BN + ReLU(shortcut) + add, write out
    float bscale = gamma[o] / sqrtf(1.00001f);
    float bbeta = beta[o];
    float* ob = out + (((size_t)(b * CC + o)) * HH + row) * WW + cb + ph * 32;
    #pragma unroll
    for (int q = 0; q < 8; q++) {
        float z0, z1, z2, z3, s0, s1, s2, s3;
        unpack2(a1[2*q],   z0, z1); unpack2(a1[2*q+1], z2, z3);
        unpack2(a2[2*q],   s0, s1); unpack2(a2[2*q+1], s2, s3);
        float4 r;
        r.x = gelu_exact(z0) * bscale + bbeta + fmaxf(s0, 0.0f);
        r.y = gelu_exact(z1) * bscale + bbeta + fmaxf(s1, 0.0f);
        r.z = gelu_exact(z2) * bscale + bbeta + fmaxf(s2, 0.0f);
        r.w = gelu_exact(z3) * bscale + bbeta + fmaxf(s3, 0.0f);
        *(float4*)(ob + q * 4) = r;
    }
}

// ---------------- launch ----------------
extern "C" void kernel_launch(void* const* d_in, const int* in_sizes, int n_in,
                              void* d_out, int out_size) {
    (void)in_sizes; (void)n_in; (void)out_size;
    const float* x      = (const float*)d_in[0];
    const float* sc_w   = (const float*)d_in[1];
    const float* sc_b   = (const float*)d_in[2];
    const float* q_w    = (const float*)d_in[3];
    const float* q_b    = (const float*)d_in[4];
    const float* k_w    = (const float*)d_in[5];
    const float* k_b    = (const float*)d_in[6];
    const float* v_dw_w = (const float*)d_in[7];
    const float* v_dw_b = (const float*)d_in[8];
    const float* v_pw_w = (const float*)d_in[9];
    const float* v_pw_b = (const float*)d_in[10];
    const float* lscale = (const float*)d_in[11];
    const float* cpb_w1 = (const float*)d_in[12];
    const float* cpb_b1 = (const float*)d_in[13];
    const float* cpb_w2 = (const float*)d_in[14];
    const float* proj_w = (const float*)d_in[15];
    const float* proj_b = (const float*)d_in[16];
    const float* bn_g   = (const float*)d_in[17];
    const float* bn_b   = (const float*)d_in[18];
    float* out = (float*)d_out;

    cudaFuncSetAttribute(main_kernel, cudaFuncAttributeMaxDynamicSharedMemorySize, 131072);

    pool_kernel<<<(BB*CC*LP + 255) / 256, 256>>>(x);
    cpb_kernel<<<(CC*CC + 255) / 256, 256>>>(cpb_w1, cpb_b1, cpb_w2);
    scwT_kernel<<<(CC*CC + 255) / 256, 256>>>(sc_w);
    qk_kernel<<<dim3(BB*NHD*CC, 2), 256>>>(q_w, q_b, k_w, k_b);
    gemm_nt_kernel<<<dim3(4, 4, 32), 256>>>(0, nullptr, lscale);     // sim
    dsoftmax_kernel<<<BB*NHD*CC, 256>>>();                           // W
    wvt_kernel<<<dim3(4, 32), 256>>>(v_pw_w);                        // fold v_pw
    gemm_nt_kernel<<<dim3(4, 4, 32), 256>>>(1, proj_w, nullptr);     // Mt
    wb_kernel<<<BB*NHD, 256>>>(v_pw_b);
    cvec_kernel<<<BB*NHD, 256>>>(proj_w, proj_b);
    main_kernel<<<dim3(2, 128, 8), 512, 131072>>>(x, v_dw_w, v_dw_b, sc_b, bn_g, bn_b, out);
}

// round 7
// speedup vs baseline: 2.7459x; 2.7459x over previous
#include <cuda_runtime.h>
#include <math.h>

#define BB 8
#define CC 256
#define HH 128
#define WW 128
#define NHD 4

// ---------------- scratch (device globals; no allocation allowed) ----------------
__device__ float g_xp  [BB*CC*1024];      // pooled x [b][c][1024]
__device__ float g_qn  [32*256*256];      // normalized q [bh][c][d]
__device__ float g_kn  [32*256*256];      // normalized k [bh][c][d]
__device__ float g_sim [32*65536];        // sim -> W (in place) [bh][c][e]
__device__ float g_bias[4*65536];         // cpb bias [h][i][j]
__device__ float g_wvt [32*65536];        // (W folded with v_pw)^T [bh][f][c]
__device__ float g_mt  [32*65536];        // Mt [bh][f][o]
__device__ float g_wb  [32*256];          // W @ v_pw_b [bh][c]
__device__ float g_cvec[32*256];          // per-(bh,o) constant incl proj_b
__device__ float4 g_A1p[32*16384];        // Mt^T packed into mma-frag layout (tf32)
__device__ float4 g_A2p[16384];           // sc_w packed into mma-frag layout (tf32)

// ---------------- helpers ----------------
__device__ __forceinline__ float totf(float x) {
    unsigned u; asm("cvt.rna.tf32.f32 %0, %1;" : "=r"(u) : "f"(x));
    return __uint_as_float(u);
}
__device__ __forceinline__ float gelu_exact(float z) {
    return 0.5f * z * (1.0f + erff(z * 0.70710678118654752440f));
}
__device__ __forceinline__ void mma8(float4& c, const float4 a, const float2 b) {
    asm volatile(
        "mma.sync.aligned.m16n8k8.row.col.f32.tf32.tf32.f32 "
        "{%0,%1,%2,%3}, {%4,%5,%6,%7}, {%8,%9}, {%0,%1,%2,%3};"
        : "+f"(c.x), "+f"(c.y), "+f"(c.z), "+f"(c.w)
        : "r"(__float_as_uint(a.x)), "r"(__float_as_uint(a.y)),
          "r"(__float_as_uint(a.z)), "r"(__float_as_uint(a.w)),
          "r"(__float_as_uint(b.x)), "r"(__float_as_uint(b.y)));
}
__device__ __forceinline__ float blk256(float v, float* red, int domax) {
    #pragma unroll
    for (int off = 16; off; off >>= 1) {
        float o = __shfl_xor_sync(0xffffffffu, v, off);
        v = domax ? fmaxf(v, o) : (v + o);
    }
    int lane = threadIdx.x & 31, w = threadIdx.x >> 5;
    __syncthreads();
    if (lane == 0) red[w] = v;
    __syncthreads();
    float r = red[0];
    #pragma unroll
    for (int i = 1; i < 8; i++) r = domax ? fmaxf(r, red[i]) : (r + red[i]);
    return r;
}

// ---------------- K0: 4x4 maxpool ----------------
__global__ void pool_kernel(const float* __restrict__ x) {
    int idx = blockIdx.x * blockDim.x + threadIdx.x;
    if (idx >= BB*CC*1024) return;
    int l = idx & 1023, bc = idx >> 10;
    int py = l >> 5, px = l & 31;
    const float* xp = x + (size_t)bc * HH * WW + py * 4 * WW + px * 4;
    float m = -1e30f;
    #pragma unroll
    for (int dy = 0; dy < 4; dy++)
        #pragma unroll
        for (int dx = 0; dx < 4; dx++)
            m = fmaxf(m, xp[dy * WW + dx]);
    g_xp[idx] = m;
}

// ---------------- CPB relative-position bias ----------------
__global__ void cpb_kernel(const float* __restrict__ w1, const float* __restrict__ b1,
                           const float* __restrict__ w2) {
    int idx = blockIdx.x * blockDim.x + threadIdx.x;
    if (idx >= 65536) return;
    int j = idx & 255, i = idx >> 8;
    float d = (float)(j - i) * (8.0f / 255.0f);
    float rel = copysignf(log2f(fabsf(d) + 1.0f) * (1.0f / 3.0f), d);
    float a0 = 0.f, a1 = 0.f, a2 = 0.f, a3 = 0.f;
    #pragma unroll 8
    for (int t = 0; t < 64; t++) {
        float hdn = fmaxf(rel * w1[t] + b1[t], 0.0f);
        a0 += hdn * w2[t*4+0]; a1 += hdn * w2[t*4+1];
        a2 += hdn * w2[t*4+2]; a3 += hdn * w2[t*4+3];
    }
    g_bias[0*65536 + idx] = 1.0f / (1.0f + expf(-a0));
    g_bias[1*65536 + idx] = 1.0f / (1.0f + expf(-a1));
    g_bias[2*65536 + idx] = 1.0f / (1.0f + expf(-a2));
    g_bias[3*65536 + idx] = 1.0f / (1.0f + expf(-a3));
}

// ---------------- qk: block per (b,h,g), smem-staged, warp-per-channel ----------------
__global__ void qk2_kernel(const float* __restrict__ qw, const float* __restrict__ qb,
                           const float* __restrict__ kw, const float* __restrict__ kb) {
    extern __shared__ float sm2[];
    float* xs  = sm2;              // [64 j][256 d]
    float* wqs = sm2 + 16384;      // [64 ci][64 j]
    float* wks = wqs + 4096;
    int g = blockIdx.x, h = blockIdx.y, b = blockIdx.z;
    int tid = threadIdx.x;
    const float* src = g_xp + (((size_t)(b*256 + g*64)) << 10) + h*256;
    for (int i = tid; i < 16384; i += 256) {
        int j = i >> 8, d = i & 255;
        xs[i] = src[((size_t)j << 10) + d];
    }
    for (int i = tid; i < 4096; i += 256) {
        wqs[i] = qw[g*4096 + i];
        wks[i] = kw[g*4096 + i];
    }
    __syncthreads();
    int warp = tid >> 5, lane = tid & 31;
    int bh = b*4 + h;
    for (int it = 0; it < 8; it++) {
        int ci = warp*8 + it;
        int c = g*64 + ci;
        float aq[8] = {0,0,0,0,0,0,0,0}, ak[8] = {0,0,0,0,0,0,0,0};
        #pragma unroll 4
        for (int j = 0; j < 64; j++) {
            float wq = wqs[ci*64 + j], wk = wks[ci*64 + j];
            const float* xr = xs + j*256 + lane;
            #pragma unroll
            for (int u = 0; u < 8; u++) {
                float xv = xr[u*32];
                aq[u] = fmaf(wq, xv, aq[u]);
                ak[u] = fmaf(wk, xv, ak[u]);
            }
        }
        float qbias = qb[c], kbias = kb[c];
        float sq = 0.f, sk = 0.f;
        #pragma unroll
        for (int u = 0; u < 8; u++) {
            aq[u] += qbias; ak[u] += kbias;
            sq += aq[u]*aq[u]; sk += ak[u]*ak[u];
        }
        #pragma unroll
        for (int off = 16; off; off >>= 1) {
            sq += __shfl_xor_sync(0xffffffffu, sq, off);
            sk += __shfl_xor_sync(0xffffffffu, sk, off);
        }
        float iq = 1.0f / fmaxf(sqrtf(sq), 1e-12f);
        float ik = 1.0f / fmaxf(sqrtf(sk), 1e-12f);
        float* oq = g_qn + (((size_t)(bh*256 + c)) << 8);
        float* ok = g_kn + (((size_t)(bh*256 + c)) << 8);
        #pragma unroll
        for (int u = 0; u < 8; u++) {
            oq[u*32 + lane] = aq[u]*iq;
            ok[u*32 + lane] = ak[u]*ik;
        }
    }
}

// ---------------- batched 256x256x256 NT GEMM ----------------
__global__ void gemm_nt_kernel(int mode, const float* __restrict__ Bext,
                               const float* __restrict__ ls) {
    int z = blockIdx.z;
    const float *Az, *Bz; float* Cz; const float* bz = nullptr; float scale = 1.0f;
    if (mode == 0) {
        Az = g_qn + (size_t)z * 65536; Bz = g_kn + (size_t)z * 65536;
        Cz = g_sim + (size_t)z * 65536;
        bz = g_bias + (size_t)(z & 3) * 65536;
        scale = expf(fminf(ls[z & 3], 4.6051701859880913680f));
    } else {
        Az = g_wvt + (size_t)z * 65536; Bz = Bext;
        Cz = g_mt + (size_t)z * 65536;
    }
    int i0 = blockIdx.y * 64, j0 = blockIdx.x * 64;
    __shared__ float As[16][68], Bs[16][68];
    int t = threadIdx.x;
    int tx = t & 15, ty = t >> 4;
    float cr[4][4] = {};
    int e = t * 4, lkk = e & 15, lii = e >> 4;
    for (int k0 = 0; k0 < 256; k0 += 16) {
        float4 av = *(const float4*)(Az + (size_t)(i0 + lii) * 256 + k0 + lkk);
        float4 bv = *(const float4*)(Bz + (size_t)(j0 + lii) * 256 + k0 + lkk);
        As[lkk+0][lii] = av.x; As[lkk+1][lii] = av.y; As[lkk+2][lii] = av.z; As[lkk+3][lii] = av.w;
        Bs[lkk+0][lii] = bv.x; Bs[lkk+1][lii] = bv.y; Bs[lkk+2][lii] = bv.z; Bs[lkk+3][lii] = bv.w;
        __syncthreads();
        #pragma unroll
        for (int kk = 0; kk < 16; kk++) {
            float4 a4 = *(const float4*)&As[kk][ty * 4];
            float4 b4 = *(const float4*)&Bs[kk][tx * 4];
            float ar[4] = {a4.x, a4.y, a4.z, a4.w};
            float br[4] = {b4.x, b4.y, b4.z, b4.w};
            #pragma unroll
            for (int r = 0; r < 4; r++)
                #pragma unroll
                for (int s = 0; s < 4; s++) cr[r][s] += ar[r] * br[s];
        }
        __syncthreads();
    }
    #pragma unroll
    for (int r = 0; r < 4; r++) {
        int i = i0 + ty * 4 + r, j = j0 + tx * 4;
        float4 v;
        v.x = cr[r][0] * scale; v.y = cr[r][1] * scale;
        v.z = cr[r][2] * scale; v.w = cr[r][3] * scale;
        if (bz) {
            const float4 bb = *(const float4*)(bz + (size_t)i * 256 + j);
            v.x += bb.x; v.y += bb.y; v.z += bb.z; v.w += bb.w;
        }
        *(float4*)(Cz + (size_t)i * 256 + j) = v;
    }
}

// ---------------- double softmax ----------------
__global__ void dsoftmax_kernel() {
    float* rowp = g_sim + (size_t)blockIdx.x * 256;
    int t = threadIdx.x;
    __shared__ float red[8];
    float v = rowp[t];
    float m = blk256(v, red, 1);
    float e = expf(v - m);
    float s = blk256(e, red, 0);
    float p = e / s;
    float m2 = blk256(-p, red, 1);
    float e2 = expf(-p - m2);
    float s2 = blk256(e2, red, 0);
    rowp[t] = e2 / s2;
}

// ---------------- fold v_pw into W, transposed [bh][f][c] ----------------
__global__ void wvt_kernel(const float* __restrict__ vpw) {
    __shared__ float sw[256][65];
    int g = blockIdx.x, bh = blockIdx.y;
    const float* W = g_sim + (size_t)bh * 65536;
    int t = threadIdx.x;
    for (int it = 0; it < 64; it++) {
        int lin = it * 256 + t;
        int c = lin >> 6, ei = lin & 63;
        sw[c][ei] = W[(size_t)c * 256 + g * 64 + ei];
    }
    __syncthreads();
    const float* vw = vpw + g * 4096;
    float* outb = g_wvt + (size_t)bh * 65536 + (size_t)(g * 64) * 256 + t;
    for (int jj = 0; jj < 64; jj++) {
        float acc = 0.f;
        #pragma unroll 8
        for (int ei = 0; ei < 64; ei++) acc += sw[t][ei] * vw[ei * 64 + jj];
        outb[(size_t)jj * 256] = acc;
    }
}

// ---------------- constant vectors ----------------
__global__ void wb_kernel(const float* __restrict__ vpb) {
    int bh = blockIdx.x, c = threadIdx.x;
    const float* W = g_sim + ((size_t)bh * 256 + c) * 256;
    float acc = 0.f;
    for (int e2 = 0; e2 < 256; e2++) acc += W[e2] * vpb[e2];
    g_wb[bh * 256 + c] = acc;
}
__global__ void cvec_kernel(const float* __restrict__ pw, const float* __restrict__ pb) {
    int bh = blockIdx.x, o = threadIdx.x;
    const float* wb = g_wb + bh * 256;
    float acc = pb[o];
    for (int c = 0; c < 256; c++) acc += pw[o * 256 + c] * wb[c];
    g_cvec[bh * 256 + o] = acc;
}

// ---------------- pack A matrices into mma-fragment layout (tf32) ----------------
// layout: [ks(32)][of(16)][lane(32)] -> float4 {a0,a1,a2,a3}
// a0=A[r][c], a1=A[r+8][c], a2=A[r][c+4], a3=A[r+8][c+4], r=of*16+lane/4, c=ks*8+lane%4
__global__ void packA1_kernel() {
    int bh = blockIdx.y;
    int idx = blockIdx.x * 256 + threadIdx.x;   // 0..16383
    int ks = idx >> 9, of = (idx >> 5) & 15, lane = idx & 31;
    int o = of*16 + (lane >> 2), j = ks*8 + (lane & 3);
    const float* M = g_mt + (size_t)bh * 65536;  // A[o][j] = M[j][o]
    float4 v;
    v.x = totf(M[j*256 + o]);
    v.y = totf(M[j*256 + o + 8]);
    v.z = totf(M[(j+4)*256 + o]);
    v.w = totf(M[(j+4)*256 + o + 8]);
    g_A1p[(size_t)bh*16384 + idx] = v;
}
__global__ void packA2_kernel(const float* __restrict__ scw) {
    int idx = blockIdx.x * 256 + threadIdx.x;
    int ks = idx >> 9, of = (idx >> 5) & 15, lane = idx & 31;
    int o = of*16 + (lane >> 2), j = ks*8 + (lane & 3);
    float4 v;                                    // A[o][j] = scw[o][j]
    v.x = totf(scw[o*256 + j]);
    v.y = totf(scw[(o+8)*256 + j]);
    v.z = totf(scw[o*256 + j + 4]);
    v.w = totf(scw[(o+8)*256 + j + 4]);
    g_A2p[idx] = v;
}

// ---------------- main fused kernel: dwconv + dual TF32-mma GEMM + epilogue ----------------
// block: 1 image row x 64 cols x all 256 out chans. 256 threads = 8 warps (4 o-warps x 2 pos-warps)
__device__ __forceinline__ void produce_chunk(
    int q, int pbuf, int b, int row, int ct, int bh, int tid,
    const float* __restrict__ x, const float* __restrict__ dww,
    const float* __restrict__ dwb, float* sA, float* sB)
{
    // stage A chunk (both matrices) into smem, coalesced float4 copies
    #pragma unroll
    for (int i = 0; i < 8; i++) {
        int f4 = i * 256 + tid;
        *(float4*)(sA + (size_t)((pbuf*2 + 0)*2048 + f4)*4) = g_A1p[(size_t)bh*16384 + q*2048 + f4];
    }
    #pragma unroll
    for (int i = 0; i < 8; i++) {
        int f4 = i * 256 + tid;
        *(float4*)(sA + (size_t)((pbuf*2 + 1)*2048 + f4)*4) = g_A2p[q*2048 + f4];
    }
    // dwconv 3x3 + relu for 32 channels x 64 cols; also center x for shortcut
    int j = tid >> 3, g7 = tid & 7;
    int ch = q*32 + j;
    const float* wp = dww + ch*9;
    float w0 = wp[0], w1 = wp[1], w2 = wp[2], w3 = wp[3], w4 = wp[4],
          w5 = wp[5], w6 = wp[6], w7 = wp[7], w8 = wp[8];
    float bias = dwb[ch];
    int cg0 = ct*64 + g7*8;
    const float* xc0 = x + (size_t)(b*256 + ch) * 16384;
    float rb[3][10];
    #pragma unroll
    for (int dr = 0; dr < 3; dr++) {
        int r = row - 1 + dr;
        #pragma unroll
        for (int cc = 0; cc < 10; cc++) {
            int col = cg0 - 1 + cc;
            rb[dr][cc] = ((unsigned)r < 128u && (unsigned)col < 128u) ? xc0[r*128 + col] : 0.f;
        }
    }
    // k-interleaved column so B fragment = one LDS.64: slot 2m holds j=m, 2m+1 holds j=m+4
    int m = j & 7, kg = j >> 3;
    int colv = kg*8 + ((m < 4) ? (m*2) : ((m-4)*2 + 1));
    float* bV = sB + (size_t)((pbuf*2 + 0)*64)*34;
    float* bX = sB + (size_t)((pbuf*2 + 1)*64)*34;
    #pragma unroll
    for (int p = 0; p < 8; p++) {
        float acc = bias
            + w0*rb[0][p] + w1*rb[0][p+1] + w2*rb[0][p+2]
            + w3*rb[1][p] + w4*rb[1][p+1] + w5*rb[1][p+2]
            + w6*rb[2][p] + w7*rb[2][p+1] + w8*rb[2][p+2];
        bV[(g7*8 + p)*34 + colv] = totf(fmaxf(acc, 0.f));
        bX[(g7*8 + p)*34 + colv] = totf(rb[1][p+1]);
    }
}

__global__ void __launch_bounds__(256, 1) main_kernel(
    const float* __restrict__ x, const float* __restrict__ dww,
    const float* __restrict__ dwb, const float* __restrict__ scb,
    const float* __restrict__ gamma, const float* __restrict__ beta,
    float* __restrict__ out)
{
    extern __shared__ float sm[];
    float* sA = sm;            // 32768 floats: [buf][mat][s][of][lane][4]
    float* sB = sm + 32768;    // 8704 floats:  [buf][mat][pos][34]
    const int tid = threadIdx.x;
    const int ct = blockIdx.x, row = blockIdx.y, b = blockIdx.z;
    const int bh = b*4 + (row >> 5);
    const int lane = tid & 31, warp = tid >> 5;
    const int wo = warp >> 1, wn = warp & 1;

    float4 c1[4][4], c2[4][4];
    #pragma unroll
    for (int mf = 0; mf < 4; mf++) {
        int o0 = wo*64 + mf*16 + (lane >> 2);
        float cva = g_cvec[bh*256 + o0], cvb = g_cvec[bh*256 + o0 + 8];
        float sa = scb[o0], sb2 = scb[o0 + 8];
        #pragma unroll
        for (int nf = 0; nf < 4; nf++) {
            c1[mf][nf] = make_float4(cva, cva, cvb, cvb);
            c2[mf][nf] = make_float4(sa, sa, sb2, sb2);
        }
    }

    produce_chunk(0, 0, b, row, ct, bh, tid, x, dww, dwb, sA, sB);
    __syncthreads();
    int buf = 0;
    for (int q = 0; q < 8; q++) {
        if (q < 7) produce_chunk(q + 1, buf ^ 1, b, row, ct, bh, tid, x, dww, dwb, sA, sB);
        const float* bVs = sB + (size_t)((buf*2 + 0)*64)*34;
        const float* bXs = sB + (size_t)((buf*2 + 1)*64)*34;
        const float* a1b = sA + (size_t)((buf*2 + 0)*2048)*4;
        const float* a2b = sA + (size_t)((buf*2 + 1)*2048)*4;
        #pragma unroll
        for (int s = 0; s < 4; s++) {
            float2 bv[4], bx[4];
            #pragma unroll
            for (int nf = 0; nf < 4; nf++) {
                int pos = wn*32 + nf*8 + (lane >> 2);
                int cb = s*8 + 2*(lane & 3);
                bv[nf] = *(const float2*)(bVs + pos*34 + cb);
                bx[nf] = *(const float2*)(bXs + pos*34 + cb);
            }
            #pragma unroll
            for (int mf = 0; mf < 4; mf++) {
                float4 a1 = *(const float4*)(a1b + (size_t)(s*512 + (wo*4 + mf)*32 + lane)*4);
                float4 a2 = *(const float4*)(a2b + (size_t)(s*512 + (wo*4 + mf)*32 + lane)*4);
                #pragma unroll
                for (int nf = 0; nf < 4; nf++) {
                    mma8(c1[mf][nf], a1, bv[nf]);
                    mma8(c2[mf][nf], a2, bx[nf]);
                }
            }
        }
        __syncthreads();
        buf ^= 1;
    }

    // epilogue: GELU + BN + relu(shortcut) + add
    const float binv = rsqrtf(1.00001f);
    #pragma unroll
    for (int mf = 0; mf < 4; mf++) {
        int o0 = wo*64 + mf*16 + (lane >> 2);
        int o1 = o0 + 8;
        float bs0 = gamma[o0]*binv, bb0 = beta[o0];
        float bs1 = gamma[o1]*binv, bb1 = beta[o1];
        float* r0 = out + ((size_t)(b*256 + o0)*128 + row)*128 + ct*64;
        float* r1 = out + ((size_t)(b*256 + o1)*128 + row)*128 + ct*64;
        #pragma unroll
        for (int nf = 0; nf < 4; nf++) {
            int pos = wn*32 + nf*8 + 2*(lane & 3);
            float4 u = c1[mf][nf], v = c2[mf][nf];
            float2 w0, w1v;
            w0.x = gelu_exact(u.x)*bs0 + bb0 + fmaxf(v.x, 0.f);
            w0.y = gelu_exact(u.y)*bs0 + bb0 + fmaxf(v.y, 0.f);
            w1v.x = gelu_exact(u.z)*bs1 + bb1 + fmaxf(v.z, 0.f);
            w1v.y = gelu_exact(u.w)*bs1 + bb1 + fmaxf(v.w, 0.f);
            *(float2*)(r0 + pos) = w0;
            *(float2*)(r1 + pos) = w1v;
        }
    }
}

// ---------------- launch ----------------
extern "C" void kernel_launch(void* const* d_in, const int* in_sizes, int n_in,
                              void* d_out, int out_size) {
    (void)in_sizes; (void)n_in; (void)out_size;
    const float* x      = (const float*)d_in[0];
    const float* sc_w   = (const float*)d_in[1];
    const float* sc_b   = (const float*)d_in[2];
    const float* q_w    = (const float*)d_in[3];
    const float* q_b    = (const float*)d_in[4];
    const float* k_w    = (const float*)d_in[5];
    const float* k_b    = (const float*)d_in[6];
    const float* v_dw_w = (const float*)d_in[7];
    const float* v_dw_b = (const float*)d_in[8];
    const float* v_pw_w = (const float*)d_in[9];
    const float* v_pw_b = (const float*)d_in[10];
    const float* lscale = (const float*)d_in[11];
    const float* cpb_w1 = (const float*)d_in[12];
    const float* cpb_b1 = (const float*)d_in[13];
    const float* cpb_w2 = (const float*)d_in[14];
    const float* proj_w = (const float*)d_in[15];
    const float* proj_b = (const float*)d_in[16];
    const float* bn_g   = (const float*)d_in[17];
    const float* bn_b   = (const float*)d_in[18];
    float* out = (float*)d_out;

    cudaFuncSetAttribute(main_kernel, cudaFuncAttributeMaxDynamicSharedMemorySize, 165888);
    cudaFuncSetAttribute(qk2_kernel, cudaFuncAttributeMaxDynamicSharedMemorySize, 98304);

    pool_kernel<<<(BB*CC*1024 + 255)/256, 256>>>(x);
    cpb_kernel<<<(65536 + 255)/256, 256>>>(cpb_w1, cpb_b1, cpb_w2);
    packA2_kernel<<<64, 256>>>(sc_w);
    qk2_kernel<<<dim3(4, 4, 8), 256, 98304>>>(q_w, q_b, k_w, k_b);
    gemm_nt_kernel<<<dim3(4, 4, 32), 256>>>(0, nullptr, lscale);     // sim
    dsoftmax_kernel<<<32*256, 256>>>();                              // W
    wvt_kernel<<<dim3(4, 32), 256>>>(v_pw_w);                        // fold v_pw
    gemm_nt_kernel<<<dim3(4, 4, 32), 256>>>(1, proj_w, nullptr);     // Mt
    wb_kernel<<<32, 256>>>(v_pw_b);
    cvec_kernel<<<32, 256>>>(proj_w, proj_b);
    packA1_kernel<<<dim3(64, 32), 256>>>();
    main_kernel<<<dim3(2, 128, 8), 256, 165888>>>(x, v_dw_w, v_dw_b, sc_b, bn_g, bn_b, out);
}